// round 10
// baseline (speedup 1.0000x reference)
#include <cuda_runtime.h>
#include <cstdint>

// Problem constants
#define B_    128
#define T_    512
#define DIN   512
#define DOUT  512
#define BETA  0.95f
#define THRESH 1.0f
#define EPS_FLAG 4e-4f

#define M_TOTAL (B_ * T_)                 // 65536
#define N_SPK   ((size_t)B_ * T_ * DOUT)  // 33554432
#define MK      ((size_t)M_TOTAL * DIN)   // 33554432

// Scratch (device globals = allowed scratch)
__device__ float  g_cur[(size_t)M_TOTAL * DOUT];
__device__ int8_t g_Adig[4 * MK];
__device__ int8_t g_Wdig[4 * (size_t)DOUT * DIN];
__device__ int    g_sa[M_TOTAL];
__device__ int    g_sb[DOUT];
__device__ int    g_count;
__device__ int            g_flag_n[B_];           // per-batch flagged count
__device__ unsigned short g_flag_d[B_][DOUT];     // per-batch flagged d list

// ---------------------------------------------------------------------------
#define BM 128
#define BN 64
#define BK 32
#define NKC (DIN / BK)        // 16

#define A_PLANE   4096
#define B_PLANE   2048
#define STAGE     24576
#define SMEM_SZ   (2 * STAGE)   // 49152

static __device__ __forceinline__ uint32_t smem_u32(const void* p) {
    uint32_t a;
    asm("{ .reg .u64 t; cvta.to.shared.u64 t, %1; cvt.u32.u64 %0, t; }"
        : "=r"(a) : "l"(p));
    return a;
}

// Conflict-free layout for rows of 32 bytes (int8 k-chunk)
static __device__ __forceinline__ uint32_t off32(uint32_t R, uint32_t h) {
    return (R >> 3) * 256 + (R & 7) * 32 + (((h ^ (R >> 2)) & 1) << 4);
}

static __device__ __forceinline__ void ldsm4(uint32_t* r, uint32_t addr) {
    asm volatile("ldmatrix.sync.aligned.m8n8.x4.shared.b16 {%0,%1,%2,%3}, [%4];"
                 : "=r"(r[0]), "=r"(r[1]), "=r"(r[2]), "=r"(r[3]) : "r"(addr));
}

static __device__ __forceinline__ void mma_s8(int* c, const uint32_t* a,
                                              uint32_t b0, uint32_t b1) {
    asm volatile(
        "mma.sync.aligned.m16n8k32.row.col.s32.s8.s8.s32 "
        "{%0,%1,%2,%3}, {%4,%5,%6,%7}, {%8,%9}, {%0,%1,%2,%3};"
        : "+r"(c[0]), "+r"(c[1]), "+r"(c[2]), "+r"(c[3])
        : "r"(a[0]), "r"(a[1]), "r"(a[2]), "r"(a[3]), "r"(b0), "r"(b1));
}

static __device__ __forceinline__ void cpasync16(uint32_t dst, const void* src) {
    asm volatile("cp.async.cg.shared.global [%0], [%1], 16;"
                 :: "r"(dst), "l"(src) : "memory");
}
#define CP_COMMIT() asm volatile("cp.async.commit_group;" ::: "memory")
#define CP_WAIT(n)  asm volatile("cp.async.wait_group %0;" :: "n"(n) : "memory")

// Balanced radix-256 digits: v = d0*2^24 + d1*2^16 + d2*2^8 + d3 exactly
static __device__ __forceinline__ void dig4(int v, int& d0, int& d1, int& d2, int& d3) {
    d3 = ((v + 128) & 255) - 128; v = (v - d3) >> 8;
    d2 = ((v + 128) & 255) - 128; v = (v - d2) >> 8;
    d1 = ((v + 128) & 255) - 128; v = (v - d1) >> 8;
    d0 = v;
}

// scale exponent: max|v|*2^s in [2^29, 2^30)
static __device__ __forceinline__ int scale_exp(float mx) {
    int e;
    frexpf(mx, &e);
    int s = 30 - e;
    return s > 90 ? 90 : (s < -90 ? -90 : s);
}

// ---------------------------------------------------------------------------
// setup W: per n-row scale + digits; also zero counters
// ---------------------------------------------------------------------------
__global__ __launch_bounds__(128)
void setupW_kernel(const float* __restrict__ W) {
    const int n   = blockIdx.x;
    const int tid = threadIdx.x;
    if (n == 0 && tid == 0) g_count = 0;
    if (n < B_ && tid == 0) g_flag_n[n] = 0;

    __shared__ float red[128];
    __shared__ int ssb;
    float v[4], mx = 0.0f;
    #pragma unroll
    for (int j = 0; j < 4; j++) {
        v[j] = W[(size_t)n * DIN + tid + j * 128];
        mx = fmaxf(mx, fabsf(v[j]));
    }
    red[tid] = mx;
    __syncthreads();
    for (int s = 64; s > 0; s >>= 1) {
        if (tid < s) red[tid] = fmaxf(red[tid], red[tid + s]);
        __syncthreads();
    }
    if (tid == 0) { ssb = scale_exp(red[0]); g_sb[n] = ssb; }
    __syncthreads();
    const float sf = __int_as_float((127 + ssb) << 23);
    #pragma unroll
    for (int j = 0; j < 4; j++) {
        int iv = __float2int_rn(v[j] * sf);
        int d0, d1, d2, d3;
        dig4(iv, d0, d1, d2, d3);
        size_t idx = (size_t)n * DIN + tid + j * 128;
        g_Wdig[0 * (size_t)DOUT * DIN + idx] = (int8_t)d0;
        g_Wdig[1 * (size_t)DOUT * DIN + idx] = (int8_t)d1;
        g_Wdig[2 * (size_t)DOUT * DIN + idx] = (int8_t)d2;
        g_Wdig[3 * (size_t)DOUT * DIN + idx] = (int8_t)d3;
    }
}

// ---------------------------------------------------------------------------
// setup A: warp per m-row
// ---------------------------------------------------------------------------
__global__ __launch_bounds__(256)
void setupA_kernel(const float* __restrict__ x) {
    const int tid  = threadIdx.x;
    const int lane = tid & 31;
    const int m    = blockIdx.x * 8 + (tid >> 5);

    float v[16], mx = 0.0f;
    #pragma unroll
    for (int j = 0; j < 16; j++) {
        v[j] = x[(size_t)m * DIN + lane + j * 32];
        mx = fmaxf(mx, fabsf(v[j]));
    }
    #pragma unroll
    for (int o = 16; o > 0; o >>= 1)
        mx = fmaxf(mx, __shfl_xor_sync(0xffffffffu, mx, o));
    const int sa = scale_exp(mx);
    if (lane == 0) g_sa[m] = sa;
    const float sf = __int_as_float((127 + sa) << 23);
    #pragma unroll
    for (int j = 0; j < 16; j++) {
        int iv = __float2int_rn(v[j] * sf);
        int d0, d1, d2, d3;
        dig4(iv, d0, d1, d2, d3);
        size_t idx = (size_t)m * DIN + lane + j * 32;
        g_Adig[0 * MK + idx] = (int8_t)d0;
        g_Adig[1 * MK + idx] = (int8_t)d1;
        g_Adig[2 * MK + idx] = (int8_t)d2;
        g_Adig[3 * MK + idx] = (int8_t)d3;
    }
}

// ---------------------------------------------------------------------------
// Exact int8 GEMM: CTA 128x64, 8 warps (warp 64x16), digit classes c<=3.
// ---------------------------------------------------------------------------
__global__ __launch_bounds__(256, 1)
void gemm_kernel(const float* __restrict__ bias)
{
    __shared__ char smem[SMEM_SZ];
    const uint32_t sbase = smem_u32(smem);

    const int tid  = threadIdx.x;
    const int lane = tid & 31;
    const int wid  = tid >> 5;
    const int wm   = wid >> 2;
    const int wn   = wid & 3;
    const int n0   = blockIdx.x * BN;
    const int m0   = blockIdx.y * BM;

    int acc[4][4][2][4];
    #pragma unroll
    for (int c = 0; c < 4; c++)
        #pragma unroll
        for (int mi = 0; mi < 4; mi++)
            #pragma unroll
            for (int ni = 0; ni < 2; ni++)
                #pragma unroll
                for (int e = 0; e < 4; e++) acc[c][mi][ni][e] = 0;

    uint32_t aoff[4];
    #pragma unroll
    for (int mi = 0; mi < 4; mi++) {
        uint32_t Ra = wm * 64 + mi * 16 + ((lane >> 3) & 1) * 8 + (lane & 7);
        aoff[mi] = off32(Ra, (uint32_t)(lane >> 4));
    }
    const uint32_t boff =
        off32((uint32_t)(wn * 16 + (lane >> 4) * 8 + (lane & 7)),
              (uint32_t)((lane >> 3) & 1));

    auto prefetch = [&](int kc, int s) {
        const uint32_t As = sbase + s * STAGE;
        const uint32_t Bs = As + 4 * A_PLANE;
        #pragma unroll
        for (int it = 0; it < 4; it++) {
            int lin   = tid + it * 256;
            int plane = lin >> 8;
            int rem   = lin & 255;
            int r     = rem >> 1;
            int h     = rem & 1;
            const void* src = g_Adig + (size_t)plane * MK
                            + (size_t)(m0 + r) * DIN + kc * BK + h * 16;
            cpasync16(As + plane * A_PLANE + off32(r, h), src);
        }
        #pragma unroll
        for (int it = 0; it < 2; it++) {
            int lin   = tid + it * 256;
            int plane = lin >> 7;
            int rem   = lin & 127;
            int r     = rem >> 1;
            int h     = rem & 1;
            const void* src = g_Wdig + (size_t)plane * DOUT * DIN
                            + (size_t)(n0 + r) * DIN + kc * BK + h * 16;
            cpasync16(Bs + plane * B_PLANE + off32(r, h), src);
        }
        CP_COMMIT();
    };

    prefetch(0, 0);

    for (int kc = 0; kc < NKC; kc++) {
        const int s = kc & 1;
        if (kc + 1 < NKC) {
            prefetch(kc + 1, s ^ 1);
            CP_WAIT(1);
        } else {
            CP_WAIT(0);
        }
        __syncthreads();

        const uint32_t As = sbase + s * STAGE;
        const uint32_t Bs = As + 4 * A_PLANE;

        uint32_t bf[4][4];
        #pragma unroll
        for (int d = 0; d < 4; d++)
            ldsm4(bf[d], Bs + d * B_PLANE + boff);

        #pragma unroll
        for (int ai = 0; ai < 4; ai++) {
            uint32_t af[4][4];
            #pragma unroll
            for (int mi = 0; mi < 4; mi++)
                ldsm4(af[mi], As + ai * A_PLANE + aoff[mi]);
            #pragma unroll
            for (int bj = 0; bj < 4; bj++) {
                if (ai + bj > 3) continue;
                const int c = ai + bj;
                #pragma unroll
                for (int mi = 0; mi < 4; mi++)
                    #pragma unroll
                    for (int ni = 0; ni < 2; ni++)
                        mma_s8(acc[c][mi][ni], af[mi],
                               bf[bj][ni * 2], bf[bj][ni * 2 + 1]);
            }
        }
        __syncthreads();
    }

    // ---- epilogue: exact combine + scale + bias ----
    #pragma unroll
    for (int mi = 0; mi < 4; mi++) {
        const int r0 = m0 + wm * 64 + mi * 16 + (lane >> 2);
        const int sa0 = g_sa[r0];
        const int sa1 = g_sa[r0 + 8];
        #pragma unroll
        for (int ni = 0; ni < 2; ni++) {
            const int n = n0 + wn * 16 + ni * 8 + (lane & 3) * 2;
            const int sb0 = g_sb[n];
            const int sb1 = g_sb[n + 1];
            const float2 bv = *(const float2*)(&bias[n]);
            float ov[4];
            #pragma unroll
            for (int e = 0; e < 4; e++) {
                long long S =
                    (((long long)acc[0][mi][ni][e]) << 24)
                  + (((long long)acc[1][mi][ni][e]) << 16)
                  + (((long long)acc[2][mi][ni][e]) << 8)
                  +  ((long long)acc[3][mi][ni][e]);
                const int sa = (e >= 2) ? sa1 : sa0;
                const int sb = (e & 1) ? sb1 : sb0;
                const long long ex = (long long)(1023 + 24 - sa - sb);
                const double sc = __longlong_as_double(ex << 52);
                ov[e] = (float)((double)S * sc) + ((e & 1) ? bv.y : bv.x);
            }
            *(float2*)(&g_cur[(size_t)r0 * DOUT + n]) =
                make_float2(ov[0], ov[1]);
            *(float2*)(&g_cur[(size_t)(r0 + 8) * DOUT + n]) =
                make_float2(ov[2], ov[3]);
        }
    }
}

// ---------------------------------------------------------------------------
// LIF scan on exact currents + near-threshold flagging.
// Unflagged lanes: provably bit-identical spikes to the fp32 reference.
// ---------------------------------------------------------------------------
__global__ __launch_bounds__(256)
void scan_kernel(float* __restrict__ out)
{
    const int g = blockIdx.x * blockDim.x + threadIdx.x;
    const int b = g / DOUT;
    const int d = g % DOUT;

    const float* __restrict__ cp = g_cur + (size_t)b * T_ * DOUT + d;
    float* __restrict__       sp = out  + (size_t)b * T_ * DOUT + d;

    float mem = 0.0f;
    int cnt = 0;
    int flag = 0;

    #pragma unroll 8
    for (int t = 0; t < T_; t++) {
        float cur = cp[(size_t)t * DOUT];
        mem = BETA * mem + cur;
        flag |= (fabsf(mem - THRESH) < EPS_FLAG);
        float s = (mem > THRESH) ? 1.0f : 0.0f;
        mem -= s;
        sp[(size_t)t * DOUT] = s;
        cnt += (s > 0.5f) ? 1 : 0;
    }

    if (flag) {
        int idx = atomicAdd(&g_flag_n[b], 1);
        g_flag_d[b][idx] = (unsigned short)d;
        cnt = 0;                       // repair kernel recounts this lane
    }

    __shared__ int sh[8];
    #pragma unroll
    for (int off = 16; off > 0; off >>= 1)
        cnt += __shfl_down_sync(0xffffffffu, cnt, off);
    if ((threadIdx.x & 31) == 0) sh[threadIdx.x >> 5] = cnt;
    __syncthreads();
    if (threadIdx.x == 0) {
        int tot = 0;
        #pragma unroll
        for (int w = 0; w < 8; w++) tot += sh[w];
        atomicAdd(&g_count, tot);
    }
}

// ---------------------------------------------------------------------------
// Repair: recompute flagged lanes with the exact fp32 recipe that scored
// rel_err 0.0 (ascending-k fmaf chain + bias add + identical scan ops).
// Block per batch b; 512 threads = one per t.
// ---------------------------------------------------------------------------
__global__ __launch_bounds__(512)
void repair_kernel(const float* __restrict__ x,
                   const float* __restrict__ W,
                   const float* __restrict__ bias,
                   float* __restrict__ out)
{
    const int b = blockIdx.x;
    const int t = threadIdx.x;
    const int n = g_flag_n[b];
    if (n == 0) return;

    __shared__ float cur[T_];
    __shared__ int   scnt;

    const float* xr = x + (size_t)(b * T_ + t) * DIN;

    for (int i = 0; i < n; i++) {
        const int d = g_flag_d[b][i];
        const float* wr = W + (size_t)d * DIN;

        // ascending-k fp32 fma chain (bit-identical to the R2/R9 GEMM path)
        float acc = 0.0f;
        #pragma unroll 4
        for (int k = 0; k < DIN; k += 4) {
            float4 xv = *(const float4*)(xr + k);
            float4 wv = *(const float4*)(wr + k);
            acc = fmaf(xv.x, wv.x, acc);
            acc = fmaf(xv.y, wv.y, acc);
            acc = fmaf(xv.z, wv.z, acc);
            acc = fmaf(xv.w, wv.w, acc);
        }
        cur[t] = acc + bias[d];
        __syncthreads();

        if (t == 0) {
            float mem = 0.0f;
            int c2 = 0;
            for (int tt = 0; tt < T_; tt++) {
                float cu = cur[tt];
                mem = BETA * mem + cu;
                float s = (mem > THRESH) ? 1.0f : 0.0f;
                mem -= s;
                cur[tt] = s;
                c2 += (s > 0.5f) ? 1 : 0;
            }
            scnt = c2;
        }
        __syncthreads();

        out[(size_t)(b * T_ + t) * DOUT + d] = cur[t];
        if (t == 0) atomicAdd(&g_count, scnt);
        __syncthreads();
    }
}

__global__ void finalize_kernel(float* __restrict__ out, int out_size)
{
    if ((size_t)out_size > N_SPK)
        out[N_SPK] = (float)g_count;
}

// ---------------------------------------------------------------------------
extern "C" void kernel_launch(void* const* d_in, const int* in_sizes, int n_in,
                              void* d_out, int out_size)
{
    const float* x    = (const float*)d_in[0];   // [B, T, DIN]
    const float* W    = (const float*)d_in[1];   // [DOUT, DIN]
    const float* bias = (const float*)d_in[2];   // [DOUT]
    float* out = (float*)d_out;
    (void)in_sizes; (void)n_in;

    setupW_kernel<<<DOUT, 128>>>(W);
    setupA_kernel<<<M_TOTAL / 8, 256>>>(x);

    dim3 ggrid(DOUT / BN, M_TOTAL / BM);   // (8, 512)
    gemm_kernel<<<ggrid, 256>>>(bias);

    scan_kernel<<<(B_ * DOUT) / 256, 256>>>(out);
    repair_kernel<<<B_, 512>>>(x, W, bias, out);
    finalize_kernel<<<1, 1>>>(out, out_size);
}

// round 11
// speedup vs baseline: 3.5190x; 3.5190x over previous
#include <cuda_runtime.h>
#include <cstdint>

// Problem constants
#define B_    128
#define T_    512
#define DIN   512
#define DOUT  512
#define BETA  0.95f
#define THRESH 1.0f

#define N_SPK ((size_t)B_ * T_ * DOUT)   // 33554432

__device__ int g_count;

// ---------------------------------------------------------------------------
// Fused GEMM+scan. CTA = (n-chunk of 64, batch b). 4 t-tiles of 128.
// GEMM math: packed fma.rn.f32x2 ascending-k — bit-identical per element to
// the R9 kernel that scored rel_err 0.0.
// ---------------------------------------------------------------------------
#define BK   16
#define NKC  (DIN / BK)       // 32 k-chunks
#define LDA  132              // As row stride (floats): 128 + 4 pad
#define LDB  68               // Bs row stride (floats): 64 + 4 pad
#define LDS_STG 66            // staging row stride (floats, even for float2)

#define AS_BUF  (BK * LDA)            // 2112 floats
#define BS_BUF  (BK * LDB)            // 1088 floats
#define STG_OFF (2 * AS_BUF + 2 * BS_BUF)
#define SMEM_FLOATS (STG_OFF + 128 * LDS_STG)
#define SMEM_BYTES  (SMEM_FLOATS * 4)   // 59392

typedef unsigned long long ull;

static __device__ __forceinline__ ull splat2(float v) {
    ull r;
    asm("mov.b64 %0, {%1, %1};" : "=l"(r) : "f"(v));
    return r;
}
static __device__ __forceinline__ ull fma2(ull a, ull b, ull c) {
    ull d;
    asm("fma.rn.f32x2 %0, %1, %2, %3;" : "=l"(d) : "l"(a), "l"(b), "l"(c));
    return d;
}
static __device__ __forceinline__ float2 unpack2(ull v) {
    float lo, hi;
    asm("mov.b64 {%0, %1}, %2;" : "=f"(lo), "=f"(hi) : "l"(v));
    return make_float2(lo, hi);
}

__global__ __launch_bounds__(256, 2)
void fused_kernel(const float* __restrict__ x,
                  const float* __restrict__ W,
                  const float* __restrict__ bias,
                  float* __restrict__ out)
{
    extern __shared__ float sm[];
    float* As  = sm;                       // [2][BK*LDA]  As[k][m(t)]
    float* Bs  = sm + 2 * AS_BUF;          // [2][BK*LDB]  Bs[k][n]
    float* stg = sm + STG_OFF;             // [128][LDS_STG]

    const int tid = threadIdx.x;
    const int tx  = tid & 7;               // n microtile (8 cols)
    const int ty  = tid >> 3;              // t microtile (4 rows), 0..31
    const int n0  = blockIdx.x * 64;
    const int b   = blockIdx.y;

    // per-thread bias for its 8 columns (4 float2 pairs)
    float2 bv[4];
    #pragma unroll
    for (int j = 0; j < 4; j++)
        bv[j] = *(const float2*)(&bias[n0 + tx * 8 + 2 * j]);

    // LIF scan state (threads 0..63 own column d = n0 + tid)
    float mem = 0.0f;
    int   cnt = 0;

    // global-load coords
    const int a_row = tid >> 2;            // 0..63 (+64 on 2nd it)
    const int a_kq  = tid & 3;
    const int b_row = tid >> 2;            // 0..63
    const int b_kq  = tid & 3;

    for (int tile = 0; tile < 4; tile++) {
        const int t0 = tile * 128;
        const float* Abase = x + (size_t)(b * T_ + t0) * DIN;

        ull acc2[4][4];
        #pragma unroll
        for (int i = 0; i < 4; i++)
            #pragma unroll
            for (int j = 0; j < 4; j++) acc2[i][j] = 0ull;

        // ---- prologue: load chunk 0 into buf 0 ----
        float4 pa[2], pb;
        #pragma unroll
        for (int it = 0; it < 2; it++) {
            int row = a_row + it * 64;
            pa[it] = *(const float4*)(&Abase[(size_t)row * DIN + a_kq * 4]);
        }
        pb = *(const float4*)(&W[(size_t)(n0 + b_row) * DIN + b_kq * 4]);
        #pragma unroll
        for (int it = 0; it < 2; it++) {
            int row = a_row + it * 64;
            As[(a_kq * 4 + 0) * LDA + row] = pa[it].x;
            As[(a_kq * 4 + 1) * LDA + row] = pa[it].y;
            As[(a_kq * 4 + 2) * LDA + row] = pa[it].z;
            As[(a_kq * 4 + 3) * LDA + row] = pa[it].w;
        }
        Bs[(b_kq * 4 + 0) * LDB + b_row] = pb.x;
        Bs[(b_kq * 4 + 1) * LDB + b_row] = pb.y;
        Bs[(b_kq * 4 + 2) * LDB + b_row] = pb.z;
        Bs[(b_kq * 4 + 3) * LDB + b_row] = pb.w;
        __syncthreads();

        // ---- k-chunk mainloop ----
        for (int kc = 0; kc < NKC; kc++) {
            const int buf = kc & 1;
            const bool pf = (kc + 1 < NKC);
            if (pf) {
                const int k0 = (kc + 1) * BK;
                #pragma unroll
                for (int it = 0; it < 2; it++) {
                    int row = a_row + it * 64;
                    pa[it] = *(const float4*)(&Abase[(size_t)row * DIN + k0 + a_kq * 4]);
                }
                pb = *(const float4*)(&W[(size_t)(n0 + b_row) * DIN + k0 + b_kq * 4]);
            }

            const float* Ab = As + buf * AS_BUF;
            const float* Bb = Bs + buf * BS_BUF;
            #pragma unroll
            for (int k = 0; k < BK; k++) {
                float4 av = *(const float4*)(&Ab[k * LDA + ty * 4]);
                ulonglong2 rb0 = *(const ulonglong2*)(&Bb[k * LDB + tx * 8]);
                ulonglong2 rb1 = *(const ulonglong2*)(&Bb[k * LDB + tx * 8 + 4]);
                const float avs[4] = {av.x, av.y, av.z, av.w};
                #pragma unroll
                for (int i = 0; i < 4; i++) {
                    const ull pav = splat2(avs[i]);
                    acc2[i][0] = fma2(pav, rb0.x, acc2[i][0]);
                    acc2[i][1] = fma2(pav, rb0.y, acc2[i][1]);
                    acc2[i][2] = fma2(pav, rb1.x, acc2[i][2]);
                    acc2[i][3] = fma2(pav, rb1.y, acc2[i][3]);
                }
            }

            if (pf) {
                const int nbuf = buf ^ 1;
                float* Aw = As + nbuf * AS_BUF;
                float* Bw = Bs + nbuf * BS_BUF;
                #pragma unroll
                for (int it = 0; it < 2; it++) {
                    int row = a_row + it * 64;
                    Aw[(a_kq * 4 + 0) * LDA + row] = pa[it].x;
                    Aw[(a_kq * 4 + 1) * LDA + row] = pa[it].y;
                    Aw[(a_kq * 4 + 2) * LDA + row] = pa[it].z;
                    Aw[(a_kq * 4 + 3) * LDA + row] = pa[it].w;
                }
                Bw[(b_kq * 4 + 0) * LDB + b_row] = pb.x;
                Bw[(b_kq * 4 + 1) * LDB + b_row] = pb.y;
                Bw[(b_kq * 4 + 2) * LDB + b_row] = pb.z;
                Bw[(b_kq * 4 + 3) * LDB + b_row] = pb.w;
            }
            __syncthreads();
        }

        // ---- stage currents (add bias; fp32, same ops as R9 epilogue) ----
        #pragma unroll
        for (int i = 0; i < 4; i++) {
            const int m = ty * 4 + i;
            #pragma unroll
            for (int j = 0; j < 4; j++) {
                float2 c = unpack2(acc2[i][j]);
                *(float2*)(&stg[m * LDS_STG + tx * 8 + 2 * j]) =
                    make_float2(c.x + bv[j].x, c.y + bv[j].y);
            }
        }
        __syncthreads();

        // ---- LIF scan: threads 0..63 own column d = n0 + tid ----
        if (tid < 64) {
            float* op = out + (size_t)(b * T_ + t0) * DOUT + n0 + tid;
            float m2 = mem;
            int   c2 = 0;
            #pragma unroll 4
            for (int t = 0; t < 128; t++) {
                float cur = stg[t * LDS_STG + tid];
                m2 = BETA * m2 + cur;
                float s = (m2 > THRESH) ? 1.0f : 0.0f;
                m2 -= s;
                op[(size_t)t * DOUT] = s;
                c2 += (s > 0.5f) ? 1 : 0;
            }
            mem = m2;
            cnt += c2;
        }
        __syncthreads();
    }

    // ---- deterministic spike-count reduction ----
    if (tid < 64) {
        #pragma unroll
        for (int o = 16; o > 0; o >>= 1)
            cnt += __shfl_down_sync(0xffffffffu, cnt, o);
    }
    __shared__ int red[2];
    if (tid == 0 || tid == 32) red[tid >> 5] = cnt;
    __syncthreads();
    if (tid == 0) atomicAdd(&g_count, red[0] + red[1]);
}

__global__ void zero_count_kernel() { g_count = 0; }

__global__ void finalize_kernel(float* __restrict__ out, int out_size)
{
    if ((size_t)out_size > N_SPK)
        out[N_SPK] = (float)g_count;
}

// ---------------------------------------------------------------------------
extern "C" void kernel_launch(void* const* d_in, const int* in_sizes, int n_in,
                              void* d_out, int out_size)
{
    const float* x    = (const float*)d_in[0];   // [B, T, DIN]
    const float* W    = (const float*)d_in[1];   // [DOUT, DIN]
    const float* bias = (const float*)d_in[2];   // [DOUT]
    float* out = (float*)d_out;
    (void)in_sizes; (void)n_in;

    cudaFuncSetAttribute(fused_kernel,
                         cudaFuncAttributeMaxDynamicSharedMemorySize, SMEM_BYTES);

    zero_count_kernel<<<1, 1>>>();

    dim3 grid(DOUT / 64, B_);              // (8, 128) = 1024 CTAs
    fused_kernel<<<grid, 256, SMEM_BYTES>>>(x, W, bias, out);

    finalize_kernel<<<1, 1>>>(out, out_size);
}

// round 12
// speedup vs baseline: 5.6464x; 1.6045x over previous
#include <cuda_runtime.h>
#include <cstdint>

// Problem constants
#define B_    128
#define T_    512
#define DIN   512
#define DOUT  512
#define BETA  0.95f
#define THRESH 1.0f

#define M_TOTAL (B_ * T_)                 // 65536
#define N_SPK   ((size_t)B_ * T_ * DOUT)  // 33554432

// Scratch: currents [M, DOUT] fp32 (134 MB). __device__ global = allowed.
__device__ float g_cur[(size_t)M_TOTAL * DOUT];
__device__ int   g_count;

// ---------------------------------------------------------------------------
// GEMM tiling: 128x128x16, 256 threads, 8x8 microtile per thread.
// Packed fma.rn.f32x2 (FFMA2): two IEEE fp32 RN FMAs per instruction,
// bit-identical per lane to scalar fmaf chains in the same (ascending-k) order.
// (Proven: rel_err 0.0 at 944.6us in R9.)
// ---------------------------------------------------------------------------
#define BM 128
#define BN 128
#define BK 16
#define NKT (DIN / BK)        // 32 k-tiles
#define LDS_STRIDE 132        // padded row stride (floats) -> conflict-free reads

typedef unsigned long long ull;

static __device__ __forceinline__ ull splat2(float v) {
    ull r;
    asm("mov.b64 %0, {%1, %1};" : "=l"(r) : "f"(v));
    return r;
}
static __device__ __forceinline__ ull fma2(ull a, ull b, ull c) {
    ull d;
    asm("fma.rn.f32x2 %0, %1, %2, %3;" : "=l"(d) : "l"(a), "l"(b), "l"(c));
    return d;
}
static __device__ __forceinline__ float2 unpack2(ull v) {
    float lo, hi;
    asm("mov.b64 {%0, %1}, %2;" : "=f"(lo), "=f"(hi) : "l"(v));
    return make_float2(lo, hi);
}

__global__ __launch_bounds__(256, 2)
void gemm_kernel(const float* __restrict__ A,
                 const float* __restrict__ W,
                 const float* __restrict__ bias)
{
    __shared__ float As[2][BK * LDS_STRIDE];   // As[buf][k*132 + m]
    __shared__ float Bs[2][BK * LDS_STRIDE];   // Bs[buf][k*132 + n]

    const int tid = threadIdx.x;
    const int tx  = tid & 15;       // n microtile (8 cols)
    const int ty  = tid >> 4;       // m microtile (8 rows)
    const int m0  = blockIdx.y * BM;
    const int n0  = blockIdx.x * BN;

    // accumulators: acc2[i][j] = (C[m_i][n_{2j}], C[m_i][n_{2j+1}]) packed
    ull acc2[8][4];
    #pragma unroll
    for (int i = 0; i < 8; i++)
        #pragma unroll
        for (int j = 0; j < 4; j++) acc2[i][j] = 0ull;

    const int l_row = tid >> 2;             // 0..63 (plus +64 on second it)
    const int l_kq  = tid & 3;              // float4 within BK

    float4 pa[2], pb[2];
    #pragma unroll
    for (int it = 0; it < 2; it++) {
        int row = l_row + it * 64;
        pa[it] = *(const float4*)(&A[(size_t)(m0 + row) * DIN + l_kq * 4]);
        pb[it] = *(const float4*)(&W[(size_t)(n0 + row) * DIN + l_kq * 4]);
    }
    #pragma unroll
    for (int it = 0; it < 2; it++) {
        int row = l_row + it * 64;
        As[0][(l_kq * 4 + 0) * LDS_STRIDE + row] = pa[it].x;
        As[0][(l_kq * 4 + 1) * LDS_STRIDE + row] = pa[it].y;
        As[0][(l_kq * 4 + 2) * LDS_STRIDE + row] = pa[it].z;
        As[0][(l_kq * 4 + 3) * LDS_STRIDE + row] = pa[it].w;
        Bs[0][(l_kq * 4 + 0) * LDS_STRIDE + row] = pb[it].x;
        Bs[0][(l_kq * 4 + 1) * LDS_STRIDE + row] = pb[it].y;
        Bs[0][(l_kq * 4 + 2) * LDS_STRIDE + row] = pb[it].z;
        Bs[0][(l_kq * 4 + 3) * LDS_STRIDE + row] = pb[it].w;
    }
    __syncthreads();

    for (int kt = 0; kt < NKT; kt++) {
        const int buf = kt & 1;
        const bool pf = (kt + 1 < NKT);

        if (pf) {
            const int k0 = (kt + 1) * BK;
            #pragma unroll
            for (int it = 0; it < 2; it++) {
                int row = l_row + it * 64;
                pa[it] = *(const float4*)(&A[(size_t)(m0 + row) * DIN + k0 + l_kq * 4]);
                pb[it] = *(const float4*)(&W[(size_t)(n0 + row) * DIN + k0 + l_kq * 4]);
            }
        }

        // ---- compute on buf: ascending k, packed FFMA2 ----
        #pragma unroll
        for (int k = 0; k < BK; k++) {
            const float* ar = &As[buf][k * LDS_STRIDE + ty * 8];
            const float* br = &Bs[buf][k * LDS_STRIDE + tx * 8];
            float4 ra0 = *(const float4*)(ar);
            float4 ra1 = *(const float4*)(ar + 4);
            ulonglong2 rb0 = *(const ulonglong2*)(br);
            ulonglong2 rb1 = *(const ulonglong2*)(br + 4);
            const float ras[8] = {ra0.x, ra0.y, ra0.z, ra0.w,
                                  ra1.x, ra1.y, ra1.z, ra1.w};
            #pragma unroll
            for (int i = 0; i < 8; i++) {
                const ull pav = splat2(ras[i]);
                acc2[i][0] = fma2(pav, rb0.x, acc2[i][0]);
                acc2[i][1] = fma2(pav, rb0.y, acc2[i][1]);
                acc2[i][2] = fma2(pav, rb1.x, acc2[i][2]);
                acc2[i][3] = fma2(pav, rb1.y, acc2[i][3]);
            }
        }

        if (pf) {
            const int nbuf = buf ^ 1;
            #pragma unroll
            for (int it = 0; it < 2; it++) {
                int row = l_row + it * 64;
                As[nbuf][(l_kq * 4 + 0) * LDS_STRIDE + row] = pa[it].x;
                As[nbuf][(l_kq * 4 + 1) * LDS_STRIDE + row] = pa[it].y;
                As[nbuf][(l_kq * 4 + 2) * LDS_STRIDE + row] = pa[it].z;
                As[nbuf][(l_kq * 4 + 3) * LDS_STRIDE + row] = pa[it].w;
                Bs[nbuf][(l_kq * 4 + 0) * LDS_STRIDE + row] = pb[it].x;
                Bs[nbuf][(l_kq * 4 + 1) * LDS_STRIDE + row] = pb[it].y;
                Bs[nbuf][(l_kq * 4 + 2) * LDS_STRIDE + row] = pb[it].z;
                Bs[nbuf][(l_kq * 4 + 3) * LDS_STRIDE + row] = pb[it].w;
            }
        }
        __syncthreads();
    }

    // ---- epilogue: unpack, add bias, store ----
    const int nb = n0 + tx * 8;
    float rbias[8];
    #pragma unroll
    for (int j = 0; j < 8; j++) rbias[j] = bias[nb + j];

    #pragma unroll
    for (int i = 0; i < 8; i++) {
        const size_t m = (size_t)(m0 + ty * 8 + i);
        float2 c0 = unpack2(acc2[i][0]);
        float2 c1 = unpack2(acc2[i][1]);
        float2 c2 = unpack2(acc2[i][2]);
        float2 c3 = unpack2(acc2[i][3]);
        float4 v0 = make_float4(c0.x + rbias[0], c0.y + rbias[1],
                                c1.x + rbias[2], c1.y + rbias[3]);
        float4 v1 = make_float4(c2.x + rbias[4], c2.y + rbias[5],
                                c3.x + rbias[6], c3.y + rbias[7]);
        *(float4*)(&g_cur[m * DOUT + nb])     = v0;
        *(float4*)(&g_cur[m * DOUT + nb + 4]) = v1;
    }
}

// ---------------------------------------------------------------------------
// LIF scan, latency-fixed: __ldg (non-coherent, unordered vs stores -> loads
// hoist past the out[] stores the compiler couldn't disambiguate) + explicit
// software pipeline: load batch i+1 into registers before storing batch i.
// Arithmetic per element identical to the proven rel_err-0.0 scan.
// ---------------------------------------------------------------------------
#define SCAN_BATCH 16

__global__ __launch_bounds__(256)
void scan_kernel(float* __restrict__ out)
{
    const int g = blockIdx.x * blockDim.x + threadIdx.x;
    const int b = g >> 9;            // / DOUT
    const int d = g & 511;           // % DOUT

    const float* __restrict__ cp = g_cur + (size_t)b * T_ * DOUT + d;
    float* __restrict__       sp = out  + (size_t)b * T_ * DOUT + d;

    float mem = 0.0f;
    int cnt = 0;

    float curA[SCAN_BATCH], curB[SCAN_BATCH];

    // prologue: batch 0
    #pragma unroll
    for (int i = 0; i < SCAN_BATCH; i++)
        curA[i] = __ldg(cp + (size_t)i * DOUT);

    #pragma unroll 1
    for (int t0 = 0; t0 < T_; t0 += SCAN_BATCH) {
        float* curN = ((t0 / SCAN_BATCH) & 1) ? curA : curB;
        float* curC = ((t0 / SCAN_BATCH) & 1) ? curB : curA;
        // wait -- keep it simple and explicit:
        (void)curN; (void)curC;
        float* curCur = ((t0 / SCAN_BATCH) & 1) ? curB : curA;
        float* curNxt = ((t0 / SCAN_BATCH) & 1) ? curA : curB;

        // issue next batch loads BEFORE this batch's stores
        if (t0 + SCAN_BATCH < T_) {
            #pragma unroll
            for (int i = 0; i < SCAN_BATCH; i++)
                curNxt[i] = __ldg(cp + (size_t)(t0 + SCAN_BATCH + i) * DOUT);
        }

        #pragma unroll
        for (int i = 0; i < SCAN_BATCH; i++) {
            float cur = curCur[i];
            mem = BETA * mem + cur;
            float s = (mem > THRESH) ? 1.0f : 0.0f;
            mem -= s;
            sp[(size_t)(t0 + i) * DOUT] = s;
            cnt += (s > 0.5f) ? 1 : 0;
        }
    }

    __shared__ int sh[8];
    #pragma unroll
    for (int off = 16; off > 0; off >>= 1)
        cnt += __shfl_down_sync(0xffffffffu, cnt, off);
    if ((threadIdx.x & 31) == 0) sh[threadIdx.x >> 5] = cnt;
    __syncthreads();
    if (threadIdx.x == 0) {
        int tot = 0;
        #pragma unroll
        for (int w = 0; w < 8; w++) tot += sh[w];
        atomicAdd(&g_count, tot);
    }
}

__global__ void zero_count_kernel() { g_count = 0; }

__global__ void finalize_kernel(float* __restrict__ out, int out_size)
{
    if ((size_t)out_size > N_SPK)
        out[N_SPK] = (float)g_count;
}

// ---------------------------------------------------------------------------
extern "C" void kernel_launch(void* const* d_in, const int* in_sizes, int n_in,
                              void* d_out, int out_size)
{
    const float* x    = (const float*)d_in[0];   // [B, T, DIN]
    const float* W    = (const float*)d_in[1];   // [DOUT, DIN]
    const float* bias = (const float*)d_in[2];   // [DOUT]
    float* out = (float*)d_out;
    (void)in_sizes; (void)n_in;

    zero_count_kernel<<<1, 1>>>();

    dim3 ggrid(DOUT / BN, M_TOTAL / BM);   // (4, 512), n fastest -> x L2 reuse
    gemm_kernel<<<ggrid, 256>>>(x, W, bias);

    scan_kernel<<<(B_ * DOUT) / 256, 256>>>(out);
    finalize_kernel<<<1, 1>>>(out, out_size);
}